// round 13
// baseline (speedup 1.0000x reference)
#include <cuda_runtime.h>
#include <cuda_bf16.h>
#include <math.h>

#define BB 512
#define SS 1024
#define TT 52
#define START_TAG 50
#define END_TAG 51
#define LOG2E 1.4426950408889634f
#define LN2 0.6931471805599453

typedef unsigned long long ull;
typedef unsigned int u32;

// ---------------- device scratch (no allocations allowed) ----------------
__device__ __align__(16) float g_E[TT * TT];     // exp(transitions), f32
__device__ __align__(16) u32 g_EcBF[TT][28];     // col j: (E[2c][j],E[2c+1][j]) bf16x2
__device__ __align__(16) u32 g_ErBF[TT][28];     // row j: (E[j][2c],E[j][2c+1]) bf16x2
__device__ int    g_isU8;
__device__ __align__(16) int g_lenp[BB][4];
__device__ int    g_len[BB];
__device__ int    g_task[BB];                    // seq ids, length-descending
__device__ __align__(8) float g_alpha[BB][64];
__device__ __align__(8) float g_beta[BB][64];
__device__ int    g_Ka[BB], g_Kb[BB];
__device__ float  g_m0[BB];
__device__ double g_goldp[BB][4];
__device__ double g_final[BB];
__device__ unsigned g_cnt_len;
__device__ unsigned g_cnt_fin;

// ---------------- packed helpers ----------------
__device__ __forceinline__ ull f2pack(float lo, float hi) {
    ull r;
    asm("mov.b64 %0, {%1, %2};" : "=l"(r) : "f"(lo), "f"(hi));
    return r;
}
__device__ __forceinline__ float2 f2unpack(ull a) {
    float2 r;
    asm("mov.b64 {%0, %1}, %2;" : "=f"(r.x), "=f"(r.y) : "l"(a));
    return r;
}
__device__ __forceinline__ ull f2mul(ull a, ull b) {
    ull d;
    asm("mul.rn.f32x2 %0, %1, %2;" : "=l"(d) : "l"(a), "l"(b));
    return d;
}
__device__ __forceinline__ float ex2(float x) {
    float y;
    asm("ex2.approx.ftz.f32 %0, %1;" : "=f"(y) : "f"(x));
    return y;
}
// bf16x2: fused multiply-add, add, pack, horizontal sum
__device__ __forceinline__ u32 bffma(u32 a, u32 b, u32 c) {
    u32 d;
    asm("fma.rn.bf16x2 %0, %1, %2, %3;" : "=r"(d) : "r"(a), "r"(b), "r"(c));
    return d;
}
__device__ __forceinline__ u32 bfadd(u32 a, u32 b) {
    u32 d;
    asm("add.rn.bf16x2 %0, %1, %2;" : "=r"(d) : "r"(a), "r"(b));
    return d;
}
__device__ __forceinline__ u32 packbf(float lo, float hi) {
    u32 d;   // PTX: first source -> upper half, second -> lower half
    asm("cvt.rn.bf16x2.f32 %0, %1, %2;" : "=r"(d) : "f"(hi), "f"(lo));
    return d;
}
__device__ __forceinline__ float bf2sum(u32 p) {   // bf16 lo + hi as f32 (bit tricks)
    float lo = __int_as_float(p << 16);
    float hi = __int_as_float(p & 0xFFFF0000u);
    return lo + hi;
}

// matvec over i=0..49: 25 bf16x2 fma (rt2, no RF-bank penalty), 4 accums
__device__ __forceinline__ float matvecbf(const u32* qw, const u32* Ep) {
    u32 a0 = bffma(qw[0], Ep[0], 0u);
    u32 a1 = bffma(qw[1], Ep[1], 0u);
    u32 a2 = bffma(qw[2], Ep[2], 0u);
    u32 a3 = bffma(qw[3], Ep[3], 0u);
    #pragma unroll
    for (int c = 4; c < 24; c += 4) {
        a0 = bffma(qw[c + 0], Ep[c + 0], a0);
        a1 = bffma(qw[c + 1], Ep[c + 1], a1);
        a2 = bffma(qw[c + 2], Ep[c + 2], a2);
        a3 = bffma(qw[c + 3], Ep[c + 3], a3);
    }
    a0 = bffma(qw[24], Ep[24], a0);
    a0 = bfadd(a0, a1);
    a2 = bfadd(a2, a3);
    a0 = bfadd(a0, a2);
    return bf2sum(a0);
}

// ---------------- mask dtype + E tables (f32 + packed bf16) --------------
__global__ void k_detect(const void* mask, const float* __restrict__ tr) {
    int tid = threadIdx.x;     // 256
    if (tid == 0) { g_cnt_len = 0; g_cnt_fin = 0; }
    if (tid < 32) {
        const unsigned char* p = (const unsigned char*)mask;
        int any = 0;
        for (int b = tid; b < BB; b += 32)
            any |= (int)p[(size_t)b * SS + 1];
        #pragma unroll
        for (int o = 16; o; o >>= 1) any |= __shfl_xor_sync(0xffffffffu, any, o);
        if (tid == 0) g_isU8 = (any != 0);
    }
    for (int idx = tid; idx < TT * TT; idx += 256)
        g_E[idx] = expf(tr[idx]);
    __syncthreads();
    for (int idx = tid; idx < TT * 28; idx += 256) {
        int j = idx / 28, c = idx % 28;
        u32 vc = 0, vr = 0;
        if (c < 25) {
            vc = packbf(g_E[(2 * c) * TT + j], g_E[(2 * c + 1) * TT + j]);
            vr = packbf(g_E[j * TT + 2 * c], g_E[j * TT + 2 * c + 1]);
        }
        g_EcBF[j][c] = vc;
        g_ErBF[j][c] = vr;
    }
}

// ---------------- length partials + fused rank (last block) --------------
__global__ void k_len(const void* mask) {
    int b   = blockIdx.x >> 2;
    int c   = blockIdx.x & 3;
    int tid = threadIdx.x;       // 256
    int s   = (c << 8) + tid;
    __shared__ int sc[8];
    __shared__ bool isLast;
    bool on;
    if (g_isU8) on = ((const unsigned char*)mask)[(size_t)b * SS + s] != 0;
    else        on = ((const unsigned int*)mask)[(size_t)b * SS + s] != 0;
    unsigned bal = __ballot_sync(0xffffffffu, on);
    if ((tid & 31) == 0) sc[tid >> 5] = __popc(bal);
    __syncthreads();
    if (tid == 0) {
        int cnt = 0;
        #pragma unroll
        for (int i = 0; i < 8; i++) cnt += sc[i];
        g_lenp[b][c] = cnt;
        __threadfence();
        unsigned old = atomicAdd(&g_cnt_len, 1u);
        isLast = (old == 4 * BB - 1);
    }
    __syncthreads();
    if (!isLast) return;

    __shared__ int sl[BB];
    for (int bb = tid; bb < BB; bb += 256) {
        volatile int* lp = (volatile int*)g_lenp[bb];
        int len = lp[0] + lp[1] + lp[2] + lp[3];
        sl[bb] = len;
        g_len[bb] = len;
    }
    __syncthreads();
    for (int bb = tid; bb < BB; bb += 256) {
        int len = sl[bb];
        int r = 0;
        #pragma unroll 8
        for (int cc = 0; cc < BB; cc++) {
            int lc = sl[cc];
            r += (lc > len) || (lc == len && cc < bb);
        }
        g_task[r] = bb;
    }
}

// ---------------- gold partials: one thread per (b, s) -------------------
__global__ void k_gold2(const void* mask,
                        const float* __restrict__ feats,
                        const int* __restrict__ tags,
                        const float* __restrict__ tr) {
    int b   = blockIdx.x >> 2;
    int c   = blockIdx.x & 3;
    int tid = threadIdx.x;       // 256
    int s   = (c << 8) + tid;
    __shared__ double sg[8];

    bool on, onNext;
    if (g_isU8) {
        const unsigned char* p = (const unsigned char*)mask + (size_t)b * SS;
        on = p[s] != 0;
        onNext = (s + 1 < SS) ? (p[s + 1] != 0) : false;
    } else {
        const unsigned int* p = (const unsigned int*)mask + (size_t)b * SS;
        on = p[s] != 0;
        onNext = (s + 1 < SS) ? (p[s + 1] != 0) : false;
    }

    double term = 0.0;
    if (on) {
        const int* tg = tags + (size_t)b * SS;
        int tag  = tg[s];
        int prev = (s == 0) ? START_TAG : tg[s - 1];
        term = (double)feats[((size_t)b * SS + s) * TT + tag]
             + (double)tr[prev * TT + tag];
        if (!onNext)
            term += (double)tr[tag * TT + END_TAG];
    }
    #pragma unroll
    for (int o = 16; o; o >>= 1) term += __shfl_xor_sync(0xffffffffu, term, o);
    if ((tid & 31) == 0) sg[tid >> 5] = term;
    __syncthreads();
    if (tid == 0) {
        double acc = 0.0;
        #pragma unroll
        for (int i = 0; i < 8; i++) acc += sg[i];
        g_goldp[b][c] = acc;
    }
}

// ---------------- forward/backward scan, single-warp CTAs, bf16 matvec ---
// LPT task order; dir=cta&1. State q lives in smem as 25 bf16x2 words; the
// matvec is 2x25 HFMA2.BF16 (rt2, 32-bit regs) instead of 50 FFMA2 (rt~3-4
// from 64-bit RF banking) — the dominant chain term halves. Exact pow-2
// renorm on even steps only; Ktot bookkeeping unchanged.
__global__ void __launch_bounds__(32, 1) k_main(const float* __restrict__ feats,
                                                const float* __restrict__ tr) {
    const int cta = blockIdx.x;
    const int b = g_task[cta >> 1];
    const bool isFwd = (cta & 1) == 0;
    const int t = threadIdx.x;            // 0..31
    const bool act = (t < 25);
    const int tcl = act ? t : 24;
    const int jA = act ? 2 * t : 48;
    const int jB = act ? 2 * t + 1 : 49;
    __shared__ __align__(16) u32 shq[2][32];

    const int len = g_len[b];
    const int m = (len - 1) >> 1;
    const float* fb = feats + (size_t)b * SS * TT;
    const ull L2E2 = f2pack(LOG2E, LOG2E);
    float uA, uB;
    int Ktot = 0;

#define LOAD_QW(SRC)                                                          \
    const uint4* q4 = (const uint4*)shq[SRC];                                 \
    uint4 w0 = q4[0], w1 = q4[1], w2 = q4[2], w3 = q4[3], w4 = q4[4],         \
          w5 = q4[5];                                                         \
    u32 q24 = shq[SRC][24];                                                   \
    u32 qw[25] = {w0.x, w0.y, w0.z, w0.w, w1.x, w1.y, w1.z, w1.w,             \
                  w2.x, w2.y, w2.z, w2.w, w3.x, w3.y, w3.z, w3.w,             \
                  w4.x, w4.y, w4.z, w4.w, w5.x, w5.y, w5.z, w5.w, q24};

    if (isFwd) {
        const int L = m + 1;              // steps s=1..m
        u32 EpA[25], EpB[25];
        #pragma unroll
        for (int c = 0; c < 25; c++) {
            EpA[c] = g_EcBF[jA][c];
            EpB[c] = g_EcBF[jB][c];
        }

        float p0A = act ? (fb[jA] + tr[START_TAG * TT + jA]) : -1e30f;
        float p0B = act ? (fb[jB] + tr[START_TAG * TT + jB]) : -1e30f;
        float mx = fmaxf(p0A, p0B);
        #pragma unroll
        for (int o = 16; o; o >>= 1)
            mx = fmaxf(mx, __shfl_xor_sync(0xffffffffu, mx, o));
        const float m0 = mx;
        uA = act ? ex2((p0A - m0) * LOG2E) : 0.0f;
        uB = act ? ex2((p0B - m0) * LOG2E) : 0.0f;
        shq[0][t] = packbf(uA, uB);
        __syncwarp();

        const float2* pe = (const float2*)fb + tcl;   // stride 26 float2/step
        ull fl0 = 0, fl1 = 0, fl2 = 0, fl3 = 0;
        if (1 < L) { float2 v = pe[1 * 26]; fl0 = f2mul(f2pack(v.x, v.y), L2E2); }
        if (2 < L) { float2 v = pe[2 * 26]; fl1 = f2mul(f2pack(v.x, v.y), L2E2); }
        if (3 < L) { float2 v = pe[3 * 26]; fl2 = f2mul(f2pack(v.x, v.y), L2E2); }
        if (4 < L) { float2 v = pe[4 * 26]; fl3 = f2mul(f2pack(v.x, v.y), L2E2); }

#define FSTEP(SRC, DST, RN) {                                                 \
        float2 fc = f2unpack(fl0);                                            \
        float efA = ex2(fc.x), efB = ex2(fc.y);                               \
        fl0 = fl1; fl1 = fl2; fl2 = fl3;                                      \
        int sp = s + 4;                                                       \
        float2 nv = make_float2(0.f, 0.f);                                    \
        if (sp < L) nv = pe[sp * 26];                                         \
        fl3 = f2mul(f2pack(nv.x, nv.y), L2E2);                                \
        LOAD_QW(SRC)                                                          \
        float preA, preB;                                                     \
        if (RN) {                                                             \
            int exq = ((int)((qw[0] >> 7) & 0xFFu)) - 127;                    \
            Ktot += exq;                                                      \
            float scale = __int_as_float((127 - exq) << 23);                  \
            preA = scale * efA; preB = scale * efB;                           \
        } else { preA = efA; preB = efB; }                                    \
        uA = matvecbf(qw, EpA) * preA;                                        \
        uB = matvecbf(qw, EpB) * preB;                                        \
        shq[DST][t] = packbf(uA, uB);                                         \
        __syncwarp();                                                         \
        s++;                                                                  \
    }
        int s = 1;
        while (s + 1 < L) { FSTEP(0, 1, 1) FSTEP(1, 0, 0) }
        if (s < L) { FSTEP(0, 1, 1) }
#undef FSTEP
        if (act) ((float2*)g_alpha[b])[t] = make_float2(uA, uB);
        if (t == 0) { g_Ka[b] = Ktot; g_m0[b] = m0; }
    } else {
        const int N = len - 1 - m;        // iterations: s = len-2 .. m
        u32 EpA[25], EpB[25];
        #pragma unroll
        for (int c = 0; c < 25; c++) {
            EpA[c] = g_ErBF[jA][c];
            EpB[c] = g_ErBF[jB][c];
        }

        float EendA = g_E[jA * TT + END_TAG];
        float EendB = g_E[jB * TT + END_TAG];
        if (len >= 2) {
            const float* fl = fb + (size_t)(len - 1) * TT;
            uA = ex2(fl[jA] * LOG2E) * EendA;
            uB = ex2(fl[jB] * LOG2E) * EendB;
        } else {
            uA = EendA; uB = EendB;
        }
        if (!act) { uA = 0.f; uB = 0.f; }
        shq[0][t] = packbf(uA, uB);
        __syncwarp();

        const float2* pb = (const float2*)fb + tcl;
        ull fl0 = 0, fl1 = 0, fl2 = 0, fl3 = 0;
        if (N >= 2) { float2 v = pb[(size_t)(len - 2) * 26]; fl0 = f2mul(f2pack(v.x, v.y), L2E2); }
        if (N >= 3) { float2 v = pb[(size_t)(len - 3) * 26]; fl1 = f2mul(f2pack(v.x, v.y), L2E2); }
        if (N >= 4) { float2 v = pb[(size_t)(len - 4) * 26]; fl2 = f2mul(f2pack(v.x, v.y), L2E2); }
        if (N >= 5) { float2 v = pb[(size_t)(len - 5) * 26]; fl3 = f2mul(f2pack(v.x, v.y), L2E2); }

#define BSTEP(SRC, DST, RN) {                                                 \
        float2 fc = f2unpack(fl0);                                            \
        float efA = ex2(fc.x), efB = ex2(fc.y);                               \
        fl0 = fl1; fl1 = fl2; fl2 = fl3;                                      \
        int kk = k + 4;                                                       \
        float2 nv = make_float2(0.f, 0.f);                                    \
        if (kk <= N - 2) nv = pb[(size_t)(len - 2 - kk) * 26];                \
        fl3 = f2mul(f2pack(nv.x, nv.y), L2E2);                                \
        LOAD_QW(SRC)                                                          \
        float preA, preB;                                                     \
        if (RN) {                                                             \
            int exq = ((int)((qw[0] >> 7) & 0xFFu)) - 127;                    \
            Ktot += exq;                                                      \
            float scale = __int_as_float((127 - exq) << 23);                  \
            preA = scale * efA; preB = scale * efB;                           \
        } else { preA = efA; preB = efB; }                                    \
        uA = matvecbf(qw, EpA) * preA;                                        \
        uB = matvecbf(qw, EpB) * preB;                                        \
        shq[DST][t] = packbf(uA, uB);                                         \
        __syncwarp();                                                         \
        k++;                                                                  \
    }
        int k = 0;
        while (k + 1 < N) { BSTEP(0, 1, 1) BSTEP(1, 0, 0) }
        if (k < N) { BSTEP(0, 1, 1) }
#undef BSTEP
        if (act) ((float2*)g_beta[b])[t] = make_float2(uA, uB);
        if (t == 0) g_Kb[b] = Ktot;
    }
#undef LOAD_QW
}

// ---------------- combine + fused final reduction (last block) -----------
__global__ void k_combine(float* out) {
    int b = blockIdx.x;
    int l = threadIdx.x;   // 32
    __shared__ unsigned lastFlag;
    double d = (double)g_alpha[b][l] * (double)g_beta[b][l];
    if (l < 18)
        d += (double)g_alpha[b][l + 32] * (double)g_beta[b][l + 32];
    #pragma unroll
    for (int o = 16; o; o >>= 1) d += __shfl_xor_sync(0xffffffffu, d, o);
    if (l == 0) {
        double gold = g_goldp[b][0] + g_goldp[b][1]
                    + g_goldp[b][2] + g_goldp[b][3];
        double logZ = (double)g_m0[b] +
                      (double)(g_Ka[b] + g_Kb[b]) * LN2 + log(d);
        g_final[b] = logZ - gold;
        __threadfence();
        lastFlag = (atomicAdd(&g_cnt_fin, 1u) == BB - 1);
    }
    __syncwarp();
    unsigned isLast = __shfl_sync(0xffffffffu, lastFlag, 0);
    if (isLast) {
        volatile double* gf = (volatile double*)g_final;
        double a = 0.0;
        #pragma unroll
        for (int k = 0; k < BB / 32; k++) a += gf[l + 32 * k];
        #pragma unroll
        for (int o = 16; o; o >>= 1) a += __shfl_xor_sync(0xffffffffu, a, o);
        if (l == 0) out[0] = (float)a;
    }
}

// ---------------- launch (fork-join: gold2 overlaps k_main) ----------------
extern "C" void kernel_launch(void* const* d_in, const int* in_sizes, int n_in,
                              void* d_out, int out_size) {
    const float* feats = (const float*)d_in[0];
    const void*  mask  = d_in[1];
    const int*   tags  = (const int*)d_in[2];
    const float* tr    = (const float*)d_in[3];
    float* out = (float*)d_out;

    cudaStream_t s2 = 0;
    cudaEvent_t evA = 0, evB = 0;
    bool forked =
        (cudaStreamCreateWithFlags(&s2, cudaStreamNonBlocking) == cudaSuccess) &&
        (cudaEventCreateWithFlags(&evA, cudaEventDisableTiming) == cudaSuccess) &&
        (cudaEventCreateWithFlags(&evB, cudaEventDisableTiming) == cudaSuccess);

    k_detect<<<1, 256>>>(mask, tr);
    k_len<<<4 * BB, 256>>>(mask);         // fused rank in last block

    if (forked) {
        cudaEventRecord(evA, 0);
        cudaStreamWaitEvent(s2, evA, 0);
        k_gold2<<<4 * BB, 256, 0, s2>>>(mask, feats, tags, tr);
        k_main<<<2 * BB, 32>>>(feats, tr);
        cudaEventRecord(evB, s2);
        cudaStreamWaitEvent(0, evB, 0);
    } else {
        k_gold2<<<4 * BB, 256>>>(mask, feats, tags, tr);
        k_main<<<2 * BB, 32>>>(feats, tr);
    }

    k_combine<<<BB, 32>>>(out);           // fused final reduce in last block

    if (forked) {
        cudaEventDestroy(evA);
        cudaEventDestroy(evB);
        cudaStreamDestroy(s2);
    }
}